// round 10
// baseline (speedup 1.0000x reference)
#include <cuda_runtime.h>

// Problem shape (ParallelScan: B=4, S=4096, D=2048, fp32)
#define BB      4
#define SSEQ    4096
#define DDIM    2048

#define TPB     256          // threads per block
#define VPT     4            // floats per thread (float4)
#define TW      (TPB*VPT)    // 1024 d-columns per block tile
#define DT      (DDIM/TW)    // 2 d-tiles
#define LCH     64           // rows per chunk -> 512 blocks = single wave (all resident)
#define NCHUNK  (SSEQ/LCH)   // 64 chunks per chain
#define NCHAIN  (BB*DT)      // 8 chains
#define GRIDBLKS (NCHUNK*DT*BB)  // 512

// Scratch: chunk compositions / exclusive prefixes (2 MB each -> L2-resident).
__device__ float g_aggA[NCHAIN*NCHUNK*TW];
__device__ float g_aggB[NCHAIN*NCHUNK*TW];

// Coordination state (all reset to 0 by end of every launch -> graph-replay safe).
__device__ int          g_chain_cnt[NCHAIN];  // phase-1 completions per chain
__device__ volatile int g_done;               // chains fully scanned (release when == NCHAIN)
__device__ int          g_exit;               // exit counter for state reset

__device__ __forceinline__ float4 f4_fma(float4 a, float4 h, float4 b) {
    return make_float4(fmaf(a.x,h.x,b.x), fmaf(a.y,h.y,b.y),
                       fmaf(a.z,h.z,b.z), fmaf(a.w,h.w,b.w));
}
__device__ __forceinline__ float4 f4_mul(float4 a, float4 b) {
    return make_float4(a.x*b.x, a.y*b.y, a.z*b.z, a.w*b.w);
}

// One persistent single-wave kernel:
//   Phase 1: per-chunk composition, computed in REVERSE row order so the rows
//            phase 3 reads FIRST are the ones most recently cached in L2.
//   Phase 2: the 64th finisher of each chain scans that chain's aggregates
//            immediately (overlaps other chains' phase 1). No full barrier.
//   Release: g_done == NCHAIN  =>  every entry state is published.
//   Phase 3: forward replay of the recurrence, streaming output stores.
__global__ __launch_bounds__(TPB, 4)     // <=64 regs -> 4 blocks/SM -> all 512 resident
void scan_fused(const float* __restrict__ a,
                const float* __restrict__ b,
                const float* __restrict__ h0,
                float* __restrict__ out)
{
    const int chunk = blockIdx.x;
    const int dtile = blockIdx.y;
    const int batch = blockIdx.z;
    const int chain = batch * DT + dtile;
    const int col   = dtile * TW + threadIdx.x * VPT;
    const size_t base = ((size_t)batch * SSEQ + (size_t)chunk * LCH) * DDIM + col;

    // ===== Phase 1: suffix composition (reverse row order) =====
    // comp(i..L-1): B_i = A_{i+1}*b_i + B_{i+1};  A_i = a_i*A_{i+1}
    float4 A  = make_float4(1.f,1.f,1.f,1.f);
    float4 Bc = make_float4(0.f,0.f,0.f,0.f);

#pragma unroll 8
    for (int i = LCH - 1; i >= 1; i--) {
        float4 ra = *(const float4*)(a + base + (size_t)i * DDIM);
        float4 rb = *(const float4*)(b + base + (size_t)i * DDIM);
        Bc = f4_fma(A, rb, Bc);    // B = A*b_i + B   (old A)
        A  = f4_mul(A, ra);        // A = a_i*A
    }
    {   // row 0 last (hottest in L2 for phase 3). Chunk 0 folds h0 here.
        float4 ra = *(const float4*)(a + base);
        float4 rb = *(const float4*)(b + base);
        if (chunk == 0) {
            float4 h = *(const float4*)(h0 + (size_t)batch * DDIM + col);
            rb = f4_fma(ra, h, rb);            // b0' = b0 + a0*h0
        }
        Bc = f4_fma(A, rb, Bc);
        A  = f4_mul(A, ra);
    }

    const int slot = (chain * NCHUNK + chunk) * TW + threadIdx.x * VPT;
    *(float4*)(g_aggA + slot) = A;
    *(float4*)(g_aggB + slot) = Bc;

    // ===== Chain-completion election: 64th finisher scans its chain =====
    __threadfence();              // release aggregate stores
    __syncthreads();              // whole block's stores done before the bump
    __shared__ int s_scan;
    if (threadIdx.x == 0) {
        int prev = atomicAdd(&g_chain_cnt[chain], 1);
        s_scan = (prev == NCHUNK - 1);
        if (s_scan) g_chain_cnt[chain] = 0;     // reset for next replay
    }
    __syncthreads();

    if (s_scan) {
        __threadfence();          // acquire: see all 64 blocks' aggregates

        // ===== Phase 2: per-chain exclusive prefix scan (column-parallel) =====
        const int cbase = chain * NCHUNK * TW + threadIdx.x * VPT;
        float4 cB = make_float4(0.f,0.f,0.f,0.f);

        float4 pA[4], pB[4];      // depth-4 prefetch ring (L2-hot loads)
#pragma unroll
        for (int j = 0; j < 4; j++) {
            pA[j] = *(const float4*)(g_aggA + cbase + j * TW);
            pB[j] = *(const float4*)(g_aggB + cbase + j * TW);
        }
        int s = cbase;
#pragma unroll 4
        for (int k = 0; k < NCHUNK; k++) {
            float4 gA = pA[k & 3], gB = pB[k & 3];
            if (k + 4 < NCHUNK) {
                pA[k & 3] = *(const float4*)(g_aggA + s + 4 * TW);
                pB[k & 3] = *(const float4*)(g_aggB + s + 4 * TW);
            }
            *(float4*)(g_aggB + s) = cB;          // exclusive prefix (entry state)
            cB = f4_fma(gA, cB, gB);              // carry = gA*carry + gB
            s += TW;
        }

        __threadfence();          // release prefix stores
        __syncthreads();          // all columns written before announcing
        if (threadIdx.x == 0) atomicAdd((int*)&g_done, 1);
    }

    // ===== Release: wait until all chains are scanned =====
    if (threadIdx.x == 0) {
        while (g_done < NCHAIN) __nanosleep(64);
        __threadfence();          // acquire: see every chain's prefixes
    }
    __syncthreads();

    // ===== Phase 3: forward replay with entry state, streaming output =====
    // Replays from RAW b, so chunk 0's true entry state is h0 (excB there is 0).
    float4 h;
    if (chunk == 0) {
        h = *(const float4*)(h0 + (size_t)batch * DDIM + col);
    } else {
        h = *(const float4*)(g_aggB + slot);
    }

#pragma unroll 4
    for (int i = 0; i < LCH; i++) {
        float4 ra = __ldcs((const float4*)(a + base + (size_t)i * DDIM));
        float4 rb = __ldcs((const float4*)(b + base + (size_t)i * DDIM));
        h = f4_fma(ra, h, rb);
        __stcs((float4*)(out + base + (size_t)i * DDIM), h);
    }

    // ===== State reset for graph replay (last block to exit cleans up) =====
    __syncthreads();
    if (threadIdx.x == 0) {
        int prev = atomicAdd(&g_exit, 1);
        if (prev == GRIDBLKS - 1) {
            g_exit = 0;
            g_done = 0;           // all blocks have passed the wait already
        }
    }
}

extern "C" void kernel_launch(void* const* d_in, const int* in_sizes, int n_in,
                              void* d_out, int out_size)
{
    const float* a  = (const float*)d_in[0];
    const float* b  = (const float*)d_in[1];
    const float* h0 = (const float*)d_in[2];
    float* out = (float*)d_out;

    dim3 grid(NCHUNK, DT, BB);
    scan_fused<<<grid, TPB>>>(a, b, h0, out);
}

// round 11
// speedup vs baseline: 1.0021x; 1.0021x over previous
#include <cuda_runtime.h>

// Problem shape (ParallelScan: B=4, S=4096, D=2048, fp32)
#define BB      4
#define SSEQ    4096
#define DDIM    2048

#define TPB     256          // threads per block
#define VPT     4            // floats per thread (float4)
#define TW      (TPB*VPT)    // 1024 d-columns per block tile
#define DT      (DDIM/TW)    // 2 d-tiles
#define LCH     64           // rows per chunk -> 512 blocks = single wave (all resident)
#define NCHUNK  (SSEQ/LCH)   // 64 chunks per chain
#define NCHAIN  (BB*DT)      // 8 chains
#define GRIDBLKS (NCHUNK*DT*BB)  // 512
#define GSZ     16           // scan progress-publication granularity (chunks)

// Scratch: chunk compositions / exclusive prefixes (2 MB each -> L2-resident).
__device__ float g_aggA[NCHAIN*NCHUNK*TW];
__device__ float g_aggB[NCHAIN*NCHUNK*TW];

// Coordination state (all reset to 0 by end of every launch -> graph-replay safe).
__device__ int          g_chain_cnt[NCHAIN];  // phase-1 completions per chain
__device__ volatile int g_prog[NCHAIN];       // scan progress per chain (chunks published)
__device__ int          g_exit;               // exit counter for state reset

__device__ __forceinline__ float4 f4_fma(float4 a, float4 h, float4 b) {
    return make_float4(fmaf(a.x,h.x,b.x), fmaf(a.y,h.y,b.y),
                       fmaf(a.z,h.z,b.z), fmaf(a.w,h.w,b.w));
}
__device__ __forceinline__ float4 f4_mul(float4 a, float4 b) {
    return make_float4(a.x*b.x, a.y*b.y, a.z*b.z, a.w*b.w);
}

// One persistent single-wave kernel with PER-CHAIN, PER-GROUP release:
//   Phase 1: per-chunk composition in REVERSE row order (rows phase 3 reads
//            first are the most recently L2-cached).
//   Phase 2: 64th finisher of each chain scans that chain, publishing progress
//            every GSZ chunks.
//   Phase 3: block k of chain c waits only for g_prog[c] > k, then replays.
//            Chunk-0 blocks never wait (entry state is h0).
__global__ __launch_bounds__(TPB, 4)     // <=64 regs -> 4 blocks/SM -> all 512 resident
void scan_fused(const float* __restrict__ a,
                const float* __restrict__ b,
                const float* __restrict__ h0,
                float* __restrict__ out)
{
    const int chunk = blockIdx.x;
    const int dtile = blockIdx.y;
    const int batch = blockIdx.z;
    const int chain = batch * DT + dtile;
    const int col   = dtile * TW + threadIdx.x * VPT;
    const size_t base = ((size_t)batch * SSEQ + (size_t)chunk * LCH) * DDIM + col;

    // ===== Phase 1: suffix composition (reverse row order) =====
    // comp(i..L-1): B_i = A_{i+1}*b_i + B_{i+1};  A_i = a_i*A_{i+1}
    float4 A  = make_float4(1.f,1.f,1.f,1.f);
    float4 Bc = make_float4(0.f,0.f,0.f,0.f);

#pragma unroll 8
    for (int i = LCH - 1; i >= 1; i--) {
        float4 ra = *(const float4*)(a + base + (size_t)i * DDIM);
        float4 rb = *(const float4*)(b + base + (size_t)i * DDIM);
        Bc = f4_fma(A, rb, Bc);    // B = A*b_i + B   (old A)
        A  = f4_mul(A, ra);        // A = a_i*A
    }
    {   // row 0 last (hottest in L2 for phase 3). Chunk 0 folds h0 here.
        float4 ra = *(const float4*)(a + base);
        float4 rb = *(const float4*)(b + base);
        if (chunk == 0) {
            float4 h = *(const float4*)(h0 + (size_t)batch * DDIM + col);
            rb = f4_fma(ra, h, rb);            // b0' = b0 + a0*h0
        }
        Bc = f4_fma(A, rb, Bc);
        A  = f4_mul(A, ra);
    }

    const int slot = (chain * NCHUNK + chunk) * TW + threadIdx.x * VPT;
    *(float4*)(g_aggA + slot) = A;
    *(float4*)(g_aggB + slot) = Bc;

    // ===== Chain-completion election: 64th finisher scans its chain =====
    __threadfence();              // release aggregate stores
    __syncthreads();              // whole block's stores done before the bump
    __shared__ int s_scan;
    if (threadIdx.x == 0) {
        int prev = atomicAdd(&g_chain_cnt[chain], 1);
        s_scan = (prev == NCHUNK - 1);
        if (s_scan) g_chain_cnt[chain] = 0;     // reset for next replay
    }
    __syncthreads();

    if (s_scan) {
        __threadfence();          // acquire: see all 64 blocks' aggregates

        // ===== Phase 2: per-chain exclusive prefix scan, grouped publication ===
        const int cbase = chain * NCHUNK * TW + threadIdx.x * VPT;
        float4 cB = make_float4(0.f,0.f,0.f,0.f);

        float4 pA[4], pB[4];      // depth-4 prefetch ring (L2-hot loads)
#pragma unroll
        for (int j = 0; j < 4; j++) {
            pA[j] = *(const float4*)(g_aggA + cbase + j * TW);
            pB[j] = *(const float4*)(g_aggB + cbase + j * TW);
        }
        int s = cbase;
        for (int g = 0; g < NCHUNK; g += GSZ) {
#pragma unroll
            for (int kk = 0; kk < GSZ; kk++) {
                const int k = g + kk;
                float4 gA = pA[k & 3], gB = pB[k & 3];
                if (k + 4 < NCHUNK) {
                    pA[k & 3] = *(const float4*)(g_aggA + s + 4 * TW);
                    pB[k & 3] = *(const float4*)(g_aggB + s + 4 * TW);
                }
                *(float4*)(g_aggB + s) = cB;      // exclusive prefix (entry state)
                cB = f4_fma(gA, cB, gB);          // carry = gA*carry + gB
                s += TW;
            }
            // publish progress: prefixes for chunks < g+GSZ are visible
            __threadfence();      // release the group's prefix stores
            __syncthreads();      // ALL columns of this group written
            if (threadIdx.x == 0) atomicExch((int*)&g_prog[chain], g + GSZ);
        }
    }

    // ===== Per-block release: wait only for own entry state =====
    if (chunk > 0) {
        if (threadIdx.x == 0) {
            while (g_prog[chain] <= chunk) __nanosleep(64);
            __threadfence();      // acquire: see the prefix data
        }
        __syncthreads();
    }

    // ===== Phase 3: forward replay with entry state, streaming output =====
    // Replays from RAW b, so chunk 0's true entry state is h0 (excB there is 0).
    float4 h;
    if (chunk == 0) {
        h = *(const float4*)(h0 + (size_t)batch * DDIM + col);
    } else {
        h = *(const float4*)(g_aggB + slot);
    }

#pragma unroll 4
    for (int i = 0; i < LCH; i++) {
        float4 ra = __ldcs((const float4*)(a + base + (size_t)i * DDIM));
        float4 rb = __ldcs((const float4*)(b + base + (size_t)i * DDIM));
        h = f4_fma(ra, h, rb);
        __stcs((float4*)(out + base + (size_t)i * DDIM), h);
    }

    // ===== State reset for graph replay (last block to exit cleans up). ======
    // Safe: every block passed its wait before reaching here, so clearing
    // progress cannot strand a waiter.
    __syncthreads();
    if (threadIdx.x == 0) {
        int prev = atomicAdd(&g_exit, 1);
        if (prev == GRIDBLKS - 1) {
            g_exit = 0;
#pragma unroll
            for (int c = 0; c < NCHAIN; c++) g_prog[c] = 0;
        }
    }
}

extern "C" void kernel_launch(void* const* d_in, const int* in_sizes, int n_in,
                              void* d_out, int out_size)
{
    const float* a  = (const float*)d_in[0];
    const float* b  = (const float*)d_in[1];
    const float* h0 = (const float*)d_in[2];
    float* out = (float*)d_out;

    dim3 grid(NCHUNK, DT, BB);
    scan_fused<<<grid, TPB>>>(a, b, h0, out);
}